// round 2
// baseline (speedup 1.0000x reference)
#include <cuda_runtime.h>
#include <math.h>
#include <stdint.h>

#define SQ 200
#define BB 1024
#define DD 128
#define NL1 80
#define NL2 40
#define M_TOT (SQ*BB)   // 204800

// scratch (allocation-free rule: __device__ globals)
__device__ float g_H1[M_TOT*NL1];
__device__ float g_H2[M_TOT*NL2];
__device__ float g_logits[M_TOT];
__device__ float g_mean1[BB*NL1];
__device__ float g_istd1[BB*NL1];
__device__ float g_mean2[BB*NL2];
__device__ float g_istd2[BB*NL2];
__device__ int   g_mask_mode;   // 0=uint8, 1=int32, 2=float32

// ---------------------------------------------------------------------------
// K0: classify mask buffer dtype from its first 256 32-bit words.
//  int32 0/1 mask  -> every word in {0,1}
//  float32 0/1     -> every word in {0x00000000, 0x3F800000}
//  uint8 packed    -> words contain packed 0x01 bytes -> neither of the above
// Deterministic for fixed input; graph-capturable.
// ---------------------------------------------------------------------------
__global__ void k0_detect_mask(const void* __restrict__ mask)
{
    const unsigned int* w = (const unsigned int*)mask;
    bool i32 = true, f32 = true;
    for (int i = threadIdx.x; i < 256; i += 32) {
        unsigned int v = w[i];
        if (v > 1u) i32 = false;
        if (v != 0u && v != 0x3F800000u) f32 = false;
    }
    i32 = __all_sync(0xffffffffu, i32);
    f32 = __all_sync(0xffffffffu, f32);
    if (threadIdx.x == 0) g_mask_mode = i32 ? 1 : (f32 ? 2 : 0);
}

// ---------------------------------------------------------------------------
// K1: per-query-row effective GEMM.
// block b2 handles rows m in [b2*200, b2*200+200):
//   pre1[m,n] = qa[n] + sum_d facts[m,d] * wef[d,n]
// where wef[d,n] = W1[128+d,n] - W1[384+d,n] + q[d]*W1[256+d,n]
//       qa[n]   = b1[n] + sum_d q[d]*(W1[d,n] + W1[384+d,n])
// ---------------------------------------------------------------------------
__global__ __launch_bounds__(320) void k1_gemm1(
    const float* __restrict__ query, const float* __restrict__ facts,
    const float* __restrict__ W1, const float* __restrict__ b1v)
{
    extern __shared__ float sm[];
    float* q   = sm;                      // 128
    float* qa  = sm + 128;                // 80
    float* wef = sm + 208;                // 128*80
    float* fs  = sm + 208 + DD*NL1;       // 128*68 (facts chunk, transposed, padded)
    const int tid = threadIdx.x;
    const int b2  = blockIdx.x;

    if (tid < DD) q[tid] = query[b2*DD + tid];
    __syncthreads();

    for (int i = tid; i < DD*NL1; i += 320) {
        int d = i / NL1, n = i - d*NL1;
        wef[i] = W1[(DD+d)*NL1 + n] - W1[(3*DD+d)*NL1 + n] + q[d]*W1[(2*DD+d)*NL1 + n];
    }
    if (tid < NL1) {
        float s = b1v[tid];
        #pragma unroll 4
        for (int d = 0; d < DD; d++)
            s += q[d]*(W1[d*NL1 + tid] + W1[(3*DD+d)*NL1 + tid]);
        qa[tid] = s;
    }
    __syncthreads();

    const int tx = tid & 15;   // m-subtile (4 rows each -> 64 rows)
    const int ty = tid >> 4;   // 0..19, n-subtile (4 cols each -> 80 cols)

    for (int mb = 0; mb < SQ; mb += 64) {
        const int rows = min(64, SQ - mb);
        const float* fp = facts + (size_t)(b2*SQ + mb)*DD;
        for (int i = tid; i < 64*DD; i += 320) {
            int r = i >> 7, d = i & 127;
            fs[d*68 + r] = (r < rows) ? fp[i] : 0.0f;
        }
        __syncthreads();

        float acc[4][4];
        #pragma unroll
        for (int i = 0; i < 4; i++)
            #pragma unroll
            for (int j = 0; j < 4; j++) acc[i][j] = 0.0f;

        #pragma unroll 4
        for (int d = 0; d < DD; d++) {
            const float4 fv = *reinterpret_cast<const float4*>(fs + d*68 + (tx<<2));
            const float4 wv = *reinterpret_cast<const float4*>(wef + d*NL1 + (ty<<2));
            const float f4[4] = {fv.x, fv.y, fv.z, fv.w};
            const float w4[4] = {wv.x, wv.y, wv.z, wv.w};
            #pragma unroll
            for (int i = 0; i < 4; i++)
                #pragma unroll
                for (int j = 0; j < 4; j++)
                    acc[i][j] = fmaf(f4[i], w4[j], acc[i][j]);
        }

        const float4 qv = *reinterpret_cast<const float4*>(qa + (ty<<2));
        #pragma unroll
        for (int i = 0; i < 4; i++) {
            int r = (tx<<2) + i;
            if (mb + r < SQ) {
                float4 o = make_float4(acc[i][0]+qv.x, acc[i][1]+qv.y,
                                       acc[i][2]+qv.z, acc[i][3]+qv.w);
                *reinterpret_cast<float4*>(g_H1 + (size_t)(b2*SQ + mb + r)*NL1 + (ty<<2)) = o;
            }
        }
        __syncthreads();
    }
}

// ---------------------------------------------------------------------------
// stats over the S axis: element (s,b,l) lives at s*(B*L) + (b*L+l).
// thread tid = b*L+l sums a column (coalesced across threads).
// torch-style unbiased std (ddof=1).
// ---------------------------------------------------------------------------
__global__ void k2_stats1()
{
    int tid = blockIdx.x*blockDim.x + threadIdx.x;
    if (tid >= BB*NL1) return;
    const float* p = g_H1 + tid;
    float s = 0.0f, ss = 0.0f;
    #pragma unroll 8
    for (int i = 0; i < SQ; i++) { float v = p[(size_t)i*BB*NL1]; s += v; ss += v*v; }
    float mu  = s * (1.0f/SQ);
    float var = fmaxf((ss - s*mu) * (1.0f/(SQ-1)), 1e-20f);
    g_mean1[tid] = mu;
    g_istd1[tid] = rsqrtf(var);
}

__global__ void k4_stats2()
{
    int tid = blockIdx.x*blockDim.x + threadIdx.x;
    if (tid >= BB*NL2) return;
    const float* p = g_H2 + tid;
    float s = 0.0f, ss = 0.0f;
    #pragma unroll 8
    for (int i = 0; i < SQ; i++) { float v = p[(size_t)i*BB*NL2]; s += v; ss += v*v; }
    float mu  = s * (1.0f/SQ);
    float var = fmaxf((ss - s*mu) * (1.0f/(SQ-1)), 1e-20f);
    g_mean2[tid] = mu;
    g_istd2[tid] = rsqrtf(var);
}

// ---------------------------------------------------------------------------
// K3: dice(H1) @ W2 + b2 -> H2.  128 rows per block, K=80, N=40 in smem.
// ---------------------------------------------------------------------------
__global__ __launch_bounds__(320) void k3_dice_gemm2(
    const float* __restrict__ W2, const float* __restrict__ b2v,
    const float* __restrict__ a1p)
{
    extern __shared__ float sm[];
    float* hs  = sm;               // 80 * 132 (diced H1, transposed, padded)
    float* w2s = sm + NL1*132;     // 80*40
    float* bs  = w2s + NL1*NL2;    // 40
    const int tid = threadIdx.x;
    const int m0  = blockIdx.x * 128;
    const float alpha = a1p[0];

    for (int i = tid; i < NL1*NL2; i += 320) w2s[i] = W2[i];
    if (tid < NL2) bs[tid] = b2v[tid];

    for (int i = tid; i < 128*NL1; i += 320) {
        int r = i / NL1, l = i - r*NL1;
        int m = m0 + r;
        float v = g_H1[(size_t)m0*NL1 + i];
        int b = m & (BB-1);
        float z = (v - g_mean1[b*NL1 + l]) * g_istd1[b*NL1 + l];
        float p = 1.0f/(1.0f + __expf(-z));
        hs[l*132 + r] = v * (alpha + (1.0f - alpha)*p);
    }
    __syncthreads();

    const int tx = tid & 31;   // 32 * 4 = 128 rows
    const int ty = tid >> 5;   // 10 * 4 = 40 cols
    float acc[4][4];
    #pragma unroll
    for (int i = 0; i < 4; i++)
        #pragma unroll
        for (int j = 0; j < 4; j++) acc[i][j] = 0.0f;

    #pragma unroll 4
    for (int k = 0; k < NL1; k++) {
        const float4 fv = *reinterpret_cast<const float4*>(hs + k*132 + (tx<<2));
        const float4 wv = *reinterpret_cast<const float4*>(w2s + k*NL2 + (ty<<2));
        const float f4[4] = {fv.x, fv.y, fv.z, fv.w};
        const float w4[4] = {wv.x, wv.y, wv.z, wv.w};
        #pragma unroll
        for (int i = 0; i < 4; i++)
            #pragma unroll
            for (int j = 0; j < 4; j++)
                acc[i][j] = fmaf(f4[i], w4[j], acc[i][j]);
    }
    const float4 bv = *reinterpret_cast<const float4*>(bs + (ty<<2));
    #pragma unroll
    for (int i = 0; i < 4; i++) {
        int m = m0 + (tx<<2) + i;
        float4 o = make_float4(acc[i][0]+bv.x, acc[i][1]+bv.y,
                               acc[i][2]+bv.z, acc[i][3]+bv.w);
        *reinterpret_cast<float4*>(g_H2 + (size_t)m*NL2 + (ty<<2)) = o;
    }
}

// ---------------------------------------------------------------------------
// K5: logits[m] = dice(H2[m,:]) . W3 + b3
// ---------------------------------------------------------------------------
__global__ void k5_logits(const float* __restrict__ W3, const float* __restrict__ b3,
                          const float* __restrict__ a2p)
{
    int m = blockIdx.x*blockDim.x + threadIdx.x;
    if (m >= M_TOT) return;
    const float alpha = a2p[0];
    int b = m & (BB-1);
    const float* h  = g_H2 + (size_t)m*NL2;
    const float* mu = g_mean2 + b*NL2;
    const float* is = g_istd2 + b*NL2;
    float acc = 0.0f;
    #pragma unroll
    for (int l = 0; l < NL2; l++) {
        float v = h[l];
        float z = (v - mu[l]) * is[l];
        float p = 1.0f/(1.0f + __expf(-z));
        acc = fmaf(v * (alpha + (1.0f-alpha)*p), W3[l], acc);
    }
    g_logits[m] = acc + b3[0];
}

// ---------------------------------------------------------------------------
// K6: masked softmax over S per batch column, then out = w[s] * facts
// ---------------------------------------------------------------------------
__global__ __launch_bounds__(256) void k6_softmax_scale(
    const void* __restrict__ mask, const float* __restrict__ facts,
    float* __restrict__ out)
{
    __shared__ float w[SQ];
    __shared__ float red[8];
    const int b = blockIdx.x, tid = threadIdx.x;
    const float MASK_FILL = -4294967295.0f;  // float32(-2^32+1)
    const int mode = g_mask_mode;

    float my = -3.4028235e38f;
    if (tid < SQ) {
        float lg = g_logits[tid*BB + b];
        int idx = tid*BB + b;
        bool mv;
        if (mode == 1)       mv = ((const int*)mask)[idx] != 0;
        else if (mode == 2)  mv = ((const float*)mask)[idx] != 0.0f;
        else                 mv = ((const unsigned char*)mask)[idx] != 0;
        my = mv ? lg : MASK_FILL;
    }
    // block max
    float v = my;
    #pragma unroll
    for (int o = 16; o; o >>= 1) v = fmaxf(v, __shfl_xor_sync(0xffffffffu, v, o));
    if ((tid & 31) == 0) red[tid >> 5] = v;
    __syncthreads();
    float mx = red[0];
    #pragma unroll
    for (int i = 1; i < 8; i++) mx = fmaxf(mx, red[i]);
    __syncthreads();   // before reusing red

    float e = (tid < SQ) ? __expf(my - mx) : 0.0f;
    float sv = e;
    #pragma unroll
    for (int o = 16; o; o >>= 1) sv += __shfl_xor_sync(0xffffffffu, sv, o);
    if ((tid & 31) == 0) red[tid >> 5] = sv;
    __syncthreads();
    float tot = 0.0f;
    #pragma unroll
    for (int i = 0; i < 8; i++) tot += red[i];
    float inv = 1.0f / tot;
    if (tid < SQ) w[tid] = e * inv;
    __syncthreads();

    const float* fb = facts + b*DD;
    float*       ob = out   + b*DD;
    for (int i = tid; i < SQ*DD; i += 256) {
        int s = i >> 7, d = i & 127;
        size_t off = (size_t)s*BB*DD + d;
        ob[off] = w[s] * fb[off];
    }
}

// ---------------------------------------------------------------------------
extern "C" void kernel_launch(void* const* d_in, const int* in_sizes, int n_in,
                              void* d_out, int out_size)
{
    const float* query = (const float*)d_in[0];
    const float* facts = (const float*)d_in[1];
    const void*  mask  = d_in[2];
    const float* W1 = (const float*)d_in[3];
    const float* b1 = (const float*)d_in[4];
    const float* a1 = (const float*)d_in[5];
    const float* W2 = (const float*)d_in[6];
    const float* b2 = (const float*)d_in[7];
    const float* a2 = (const float*)d_in[8];
    const float* W3 = (const float*)d_in[9];
    const float* b3 = (const float*)d_in[10];
    float* out = (float*)d_out;

    const size_t sm1 = (size_t)(128 + NL1 + DD*NL1 + DD*68) * sizeof(float);   // ~76.6 KB
    const size_t sm3 = (size_t)(NL1*132 + NL1*NL2 + NL2) * sizeof(float);      // ~55.2 KB
    cudaFuncSetAttribute(k1_gemm1,      cudaFuncAttributeMaxDynamicSharedMemorySize, (int)sm1);
    cudaFuncSetAttribute(k3_dice_gemm2, cudaFuncAttributeMaxDynamicSharedMemorySize, (int)sm3);

    k0_detect_mask<<<1, 32>>>(mask);
    k1_gemm1<<<BB, 320, sm1>>>(query, facts, W1, b1);
    k2_stats1<<<(BB*NL1 + 255)/256, 256>>>();
    k3_dice_gemm2<<<M_TOT/128, 320, sm3>>>(W2, b2, a1);
    k4_stats2<<<(BB*NL2 + 255)/256, 256>>>();
    k5_logits<<<(M_TOT + 255)/256, 256>>>(W3, b3, a2);
    k6_softmax_scale<<<BB, 256>>>(mask, facts, out);
}